// round 5
// baseline (speedup 1.0000x reference)
#include <cuda_runtime.h>
#include <math.h>

#define NPTS 32768
#define RS   128
#define TILE 128
#define NTHR 512
#define NCTA 148

__device__ int g_cnt[8];
__device__ int g_list[8 * NPTS];

// ---------------- smem layout (float offsets) ----------------
#define SM_XST   0
#define SM_X0T   (256 * RS)               /* 32768 */
#define SM_WS    (SM_X0T + 112 * RS)      /* 47104 */
#define SM_WD    (SM_WS + 2 * 16 * 256)   /* 55296 */
#define SM_WC2   (SM_WD + 256)            /* 55552 */
#define SM_DENS  (SM_WC2 + 388)           /* 55940 */
#define SM_GIDX  (SM_DENS + 128)          /* 56068 */
#define SM_TOTALF (SM_GIDX + 128)
#define SMEM_BYTES (SM_TOTALF * 4)

// ---------------- packed f32x2 helpers ----------------
__device__ __forceinline__ unsigned long long dup2(float v) {
    unsigned long long r;
    asm("mov.b64 %0, {%1, %1};" : "=l"(r) : "f"(v));
    return r;
}
__device__ __forceinline__ void fma2(unsigned long long& d, unsigned long long a, unsigned long long b) {
    asm("fma.rn.f32x2 %0, %1, %2, %0;" : "+l"(d) : "l"(a), "l"(b));
}
__device__ __forceinline__ void unpack2(unsigned long long v, float& lo, float& hi) {
    asm("mov.b64 {%0, %1}, %2;" : "=f"(lo), "=f"(hi) : "l"(v));
}

// ---------------- cp.async helpers ----------------
__device__ __forceinline__ void cpasync16(unsigned saddr, const void* g, int srcsz) {
    asm volatile("cp.async.cg.shared.global [%0], [%1], 16, %2;"
                 :: "r"(saddr), "l"(g), "r"(srcsz));
}
__device__ __forceinline__ void cp_commit() { asm volatile("cp.async.commit_group;"); }
template <int n> __device__ __forceinline__ void cp_wait() {
    asm volatile("cp.async.wait_group %0;" :: "n"(n));
}

// Stage 16 rows x NCOL cols of W (rows [k0,k0+16), zero-size past K) into smem.
template <int NCOL>
__device__ __forceinline__ void stage16(float* ws, const float* __restrict__ Wg,
                                        int k0, int K, int tid) {
    if (NCOL == 256) {
        int row = tid >> 5, colb = (tid & 31) * 4;
        int gr = k0 + row;
        int sz = (gr < K) ? 16 : 0;
        const float* g = Wg + (size_t)(gr < K ? gr : 0) * 256;
        unsigned sa = (unsigned)__cvta_generic_to_shared(ws + row * 256);
        cpasync16(sa + colb * 4, g + colb, sz);
        cpasync16(sa + (colb + 128) * 4, g + colb + 128, sz);
    } else {
        int row = tid >> 5, colb = (tid & 31) * 4;
        int gr = k0 + row;
        int sz = (gr < K) ? 16 : 0;
        cpasync16((unsigned)__cvta_generic_to_shared(ws + row * 128 + colb),
                  Wg + (size_t)(gr < K ? gr : 0) * 128 + colb, sz);
    }
}

// One dense layer over a 128-point tile, 512 threads.
// Warp w (0..15): cb = w&7 (32-col block), pg = w>>3 (64-pt group).
// Lane l: cols c0 = cb*32 + (l&3)*8 ; pts p0 = pg*64 + (l>>2)*8.
// All LDS.128 are 128B-dense across the warp (no broadcast waste).
template <int NCOL>
__device__ __noinline__ void dense_layer(
    float* sm,
    const float* s1, int K1, const float* W1,
    const float* s2, int K2, const float* W2,
    const float* __restrict__ bias, int act, float* dstT)
{
    const int tid = threadIdx.x;
    const int w = tid >> 5, l = tid & 31;
    const int cb = w & 7;
    const int pg = w >> 3;
    const int c0 = cb * 32 + (l & 3) * 8;
    const int p0 = pg * 64 + (l >> 2) * 8;
    const bool active = (cb < NCOL / 32);
    float* Ws = sm + SM_WS;

    unsigned long long acc[8][4];   // [col j][pt-pair i]
    if (active) {
#pragma unroll
        for (int j = 0; j < 8; j++) {
            unsigned long long b = dup2(bias[c0 + j]);
            acc[j][0] = b; acc[j][1] = b; acc[j][2] = b; acc[j][3] = b;
        }
    }

#pragma unroll 1
    for (int s = 0; s < 2; s++) {
        const float* src = s ? s2 : s1;
        int K           = s ? K2 : K1;
        const float* Wg = s ? W2 : W1;
        if (K == 0) continue;
        int nch = (K + 15) >> 4;

        if (s) __syncthreads();   // guard buffer reuse across segments
        stage16<NCOL>(Ws, Wg, 0, K, tid);
        cp_commit();

#pragma unroll 1
        for (int c = 0; c < nch; c++) {
            cp_wait<0>();
            __syncthreads();
            // Stage next chunk AFTER the barrier: all reads of the target
            // buffer (compute(c-1)) are ordered before this write.
            if (c + 1 < nch) {
                stage16<NCOL>(Ws + ((c + 1) & 1) * 4096, Wg, (c + 1) * 16, K, tid);
                cp_commit();
            }
            if (active) {
                const float* Wb = Ws + (c & 1) * 4096;
                int kend = K - c * 16; if (kend > 16) kend = 16;
                const float* xp = src + (size_t)(c * 16) * RS + p0;
                const float* wp = Wb + c0;
#pragma unroll 2
                for (int kk = 0; kk < kend; kk++) {
                    ulonglong2 xa = *(const ulonglong2*)(xp);
                    ulonglong2 xb = *(const ulonglong2*)(xp + 4);
                    xp += RS;
                    float4 w0 = *(const float4*)(wp);
                    float4 w1 = *(const float4*)(wp + 4);
                    wp += NCOL;
                    unsigned long long wd;
                    wd = dup2(w0.x);
                    fma2(acc[0][0], xa.x, wd); fma2(acc[0][1], xa.y, wd);
                    fma2(acc[0][2], xb.x, wd); fma2(acc[0][3], xb.y, wd);
                    wd = dup2(w0.y);
                    fma2(acc[1][0], xa.x, wd); fma2(acc[1][1], xa.y, wd);
                    fma2(acc[1][2], xb.x, wd); fma2(acc[1][3], xb.y, wd);
                    wd = dup2(w0.z);
                    fma2(acc[2][0], xa.x, wd); fma2(acc[2][1], xa.y, wd);
                    fma2(acc[2][2], xb.x, wd); fma2(acc[2][3], xb.y, wd);
                    wd = dup2(w0.w);
                    fma2(acc[3][0], xa.x, wd); fma2(acc[3][1], xa.y, wd);
                    fma2(acc[3][2], xb.x, wd); fma2(acc[3][3], xb.y, wd);
                    wd = dup2(w1.x);
                    fma2(acc[4][0], xa.x, wd); fma2(acc[4][1], xa.y, wd);
                    fma2(acc[4][2], xb.x, wd); fma2(acc[4][3], xb.y, wd);
                    wd = dup2(w1.y);
                    fma2(acc[5][0], xa.x, wd); fma2(acc[5][1], xa.y, wd);
                    fma2(acc[5][2], xb.x, wd); fma2(acc[5][3], xb.y, wd);
                    wd = dup2(w1.z);
                    fma2(acc[6][0], xa.x, wd); fma2(acc[6][1], xa.y, wd);
                    fma2(acc[6][2], xb.x, wd); fma2(acc[6][3], xb.y, wd);
                    wd = dup2(w1.w);
                    fma2(acc[7][0], xa.x, wd); fma2(acc[7][1], xa.y, wd);
                    fma2(acc[7][2], xb.x, wd); fma2(acc[7][3], xb.y, wd);
                }
            }
        }
    }

    __syncthreads();   // all reads of src done before in-place writeback
    if (active) {
#pragma unroll
        for (int j = 0; j < 8; j++) {
            float v[8];
            unpack2(acc[j][0], v[0], v[1]);
            unpack2(acc[j][1], v[2], v[3]);
            unpack2(acc[j][2], v[4], v[5]);
            unpack2(acc[j][3], v[6], v[7]);
            if (act) {
#pragma unroll
                for (int q = 0; q < 8; q++) v[q] = fmaxf(v[q], 0.f);
            }
            float* d = dstT + (size_t)(c0 + j) * RS + p0;
            *(float4*)(d)     = make_float4(v[0], v[1], v[2], v[3]);
            *(float4*)(d + 4) = make_float4(v[4], v[5], v[6], v[7]);
        }
    }
    __syncthreads();
}

// ---------------- pass 0/1: zero + routing ----------------
__global__ void k_zero() { if (threadIdx.x < 8) g_cnt[threadIdx.x] = 0; }

__global__ void k_route(const float* __restrict__ pts, float* __restrict__ out) {
    int i = blockIdx.x * blockDim.x + threadIdx.x;
    if (i >= NPTS) return;
    float x = pts[3 * i], y = pts[3 * i + 1], z = pts[3 * i + 2];
    bool fg = (x >= -80.f) && (x <= 80.f) && (y >= -80.f) && (y <= 80.f)
           && (z >= -4.f) && (z <= 44.f);
    if (!fg) {
        out[i] = 0.f;
        out[NPTS + 3 * i] = 0.f; out[NPTS + 3 * i + 1] = 0.f; out[NPTS + 3 * i + 2] = 0.f;
        return;
    }
    int jx = (x > 0.f) ? 1 : 0;
    int iy = (y > 50.f) ? 3 : (y > 0.f) ? 2 : (y > -50.f) ? 1 : 0;
    int e = iy * 2 + jx;
    int pos = atomicAdd(&g_cnt[e], 1);
    g_list[e * NPTS + pos] = i;
}

// ---------------- pass 2: persistent CTAs over all (expert, tile) ----------------
__global__ void __launch_bounds__(NTHR, 1) k_mlp(
    const float* __restrict__ pts, const float* __restrict__ vds,
    const int* __restrict__ aidx, const float* __restrict__ app,
    const float* __restrict__ W0, const float* __restrict__ b0,
    const float* __restrict__ Wpre, const float* __restrict__ bpre,
    const float* __restrict__ Wskip, const float* __restrict__ bskip,
    const float* __restrict__ Wpost, const float* __restrict__ bpost,
    const float* __restrict__ Wd, const float* __restrict__ bd,
    const float* __restrict__ Wf, const float* __restrict__ bf,
    const float* __restrict__ Wc1, const float* __restrict__ bc1,
    const float* __restrict__ Wc2, const float* __restrict__ bc2,
    float* __restrict__ out)
{
    extern __shared__ float sm[];
    float* xsT  = sm + SM_XST;
    float* x0T  = sm + SM_X0T;
    float* WdS  = sm + SM_WD;
    float* Wc2S = sm + SM_WC2;
    float* dens = sm + SM_DENS;
    int*   gidx = (int*)(sm + SM_GIDX);

    const int tid = threadIdx.x;

    // Per-expert tile prefix (identical in every thread/CTA).
    int cnt8[8], tb[8], tot = 0;
#pragma unroll
    for (int e8 = 0; e8 < 8; e8++) {
        cnt8[e8] = g_cnt[e8];
        tb[e8] = tot;
        tot += (cnt8[e8] + TILE - 1) / TILE;
    }

#pragma unroll 1
    for (int tile = blockIdx.x; tile < tot; tile += gridDim.x) {
        int e = 0;
#pragma unroll
        for (int e8 = 1; e8 < 8; e8++) if (tile >= tb[e8]) e = e8;
        const int cnt  = cnt8[e];
        const int base = (tile - tb[e]) * TILE;
        const int npts = min(TILE, cnt - base);

        // ---- setup: posenc (4 threads/pt) ----
        {
            int pt = tid >> 2, q = tid & 3;
            if (pt < npts) {
                int g = g_list[e * NPTS + base + pt];
                float px = pts[3 * g], py = pts[3 * g + 1], pz = pts[3 * g + 2];
                if (q == 0) {
                    gidx[pt] = g;
                    x0T[0 * RS + pt] = px; x0T[1 * RS + pt] = py; x0T[2 * RS + pt] = pz;
                }
#pragma unroll 1
                for (int i = q; i < 10; i += 4) {
                    float f = (float)exp2((double)i * (10.0 / 9.0));  // match numpy f64->f32
                    int r = 3 + 6 * i;
                    double ax = (double)(f * px), ay = (double)(f * py), az = (double)(f * pz);
                    x0T[(r + 0) * RS + pt] = (float)sin(ax);
                    x0T[(r + 1) * RS + pt] = (float)sin(ay);
                    x0T[(r + 2) * RS + pt] = (float)sin(az);
                    x0T[(r + 3) * RS + pt] = (float)cos(ax);
                    x0T[(r + 4) * RS + pt] = (float)cos(ay);
                    x0T[(r + 5) * RS + pt] = (float)cos(az);
                }
            } else {
                if (q == 0) gidx[pt] = 0;
#pragma unroll 1
                for (int r = q; r < 63; r += 4) x0T[r * RS + pt] = 0.f;
            }
        }
        // ---- appearance (4 threads/pt) ----
        {
            int pt = tid >> 2, q = tid & 3;
            if (pt < npts) {
                int g = g_list[e * NPTS + base + pt];
                int ai = aidx[g];
                const float* a = app + ((size_t)e * 1000 + ai) * 48;
#pragma unroll 1
                for (int j = q; j < 48; j += 4) x0T[(63 + j) * RS + pt] = a[j];
            } else {
#pragma unroll 1
                for (int j = q; j < 48; j += 4) x0T[(63 + j) * RS + pt] = 0.f;
            }
        }
        // small weights
        if (tid < 256)      WdS[tid] = Wd[e * 256 + tid];
        if (tid >= 256 && tid < 512) {
            int t = tid - 256;
            Wc2S[t] = Wc2[e * 384 + t];
            if (t < 128) Wc2S[256 + t] = Wc2[e * 384 + 256 + t];
            if (t < 3)   Wc2S[384 + t] = bc2[e * 3 + t];
        }
        __syncthreads();

        // ---- trunk ----
        dense_layer<256>(sm, x0T, 111, W0 + (size_t)e * 111 * 256,
                         nullptr, 0, nullptr, b0 + e * 256, 1, xsT);
#pragma unroll 1
        for (int i = 0; i < 3; i++)
            dense_layer<256>(sm, xsT, 256, Wpre + ((size_t)e * 3 + i) * 65536,
                             nullptr, 0, nullptr, bpre + (e * 3 + i) * 256, 1, xsT);
        dense_layer<256>(sm, xsT, 256, Wskip + (size_t)e * 367 * 256,
                         x0T, 111, Wskip + (size_t)e * 367 * 256 + 256 * 256,
                         bskip + e * 256, 1, xsT);

        // ---- direnc: x0 dead after skip layer; reuse its smem for deT ----
        float* deT = x0T;
        {
            int pt = tid >> 2, q = tid & 3;
            if (pt < npts) {
                int g = gidx[pt];
                float vx = vds[3 * g], vy = vds[3 * g + 1], vz = vds[3 * g + 2];
                if (q == 0) {
                    deT[0 * RS + pt] = vx; deT[1 * RS + pt] = vy; deT[2 * RS + pt] = vz;
                }
                {
                    int i = q;
                    float f = (float)exp2((double)i * (4.0 / 3.0));
                    int r = 3 + 6 * i;
                    double ax = (double)(f * vx), ay = (double)(f * vy), az = (double)(f * vz);
                    deT[(r + 0) * RS + pt] = (float)sin(ax);
                    deT[(r + 1) * RS + pt] = (float)sin(ay);
                    deT[(r + 2) * RS + pt] = (float)sin(az);
                    deT[(r + 3) * RS + pt] = (float)cos(ax);
                    deT[(r + 4) * RS + pt] = (float)cos(ay);
                    deT[(r + 5) * RS + pt] = (float)cos(az);
                }
            } else {
#pragma unroll 1
                for (int r = q; r < 27; r += 4) deT[r * RS + pt] = 0.f;
            }
        }
        // (no barrier needed: many barriers occur before deT is consumed)

#pragma unroll 1
        for (int i = 0; i < 3; i++)
            dense_layer<256>(sm, xsT, 256, Wpost + ((size_t)e * 3 + i) * 65536,
                             nullptr, 0, nullptr, bpost + (e * 3 + i) * 256, 1, xsT);

        // ---- density head: 4 threads per point ----
        {
            int p = tid >> 2, kb = tid & 3;
            float s = 0.f;
#pragma unroll 8
            for (int j = 0; j < 64; j++) {
                int k = kb * 64 + j;
                s += xsT[k * RS + p] * WdS[k];
            }
            s += __shfl_xor_sync(0xffffffffu, s, 2);
            s += __shfl_xor_sync(0xffffffffu, s, 1);
            if (kb == 0) dens[p] = fmaxf(s + bd[e], 0.f);
        }
        __syncthreads();

        // ---- feature (no relu) ----
        dense_layer<256>(sm, xsT, 256, Wf + (size_t)e * 65536,
                         nullptr, 0, nullptr, bf + e * 256, 0, xsT);

        // ---- color hidden (relu) -> xsT rows 0..127 ----
        dense_layer<128>(sm, xsT, 256, Wc1 + (size_t)e * 283 * 128,
                         deT, 27, Wc1 + (size_t)e * 283 * 128 + 256 * 128,
                         bc1 + e * 128, 1, xsT);

        // ---- color output + final writes ----
        if (tid < 384) {
            int pt = tid / 3, cc = tid - 3 * pt;
            float s = Wc2S[384 + cc];
#pragma unroll 8
            for (int k = 0; k < 128; k++) s += xsT[k * RS + pt] * Wc2S[k * 3 + cc];
            if (pt < npts) out[NPTS + 3 * gidx[pt] + cc] = 1.f / (1.f + expf(-s));
        }
        if (tid < 128 && tid < npts) out[gidx[tid]] = dens[tid];

        __syncthreads();   // smem (xsT/x0T/gidx/dens/Wc2S) reused next tile
    }
}

// ---------------- launch ----------------
extern "C" void kernel_launch(void* const* d_in, const int* in_sizes, int n_in,
                              void* d_out, int out_size) {
    const float* pts   = (const float*)d_in[0];
    const float* vds   = (const float*)d_in[1];
    const int*   aidx  = (const int*)d_in[2];
    const float* app   = (const float*)d_in[3];
    const float* W0    = (const float*)d_in[4];
    const float* b0    = (const float*)d_in[5];
    const float* Wpre  = (const float*)d_in[6];
    const float* bpre  = (const float*)d_in[7];
    const float* Wskip = (const float*)d_in[8];
    const float* bskip = (const float*)d_in[9];
    const float* Wpost = (const float*)d_in[10];
    const float* bpost = (const float*)d_in[11];
    const float* Wd    = (const float*)d_in[12];
    const float* bd    = (const float*)d_in[13];
    const float* Wf    = (const float*)d_in[14];
    const float* bf    = (const float*)d_in[15];
    const float* Wc1   = (const float*)d_in[16];
    const float* bc1   = (const float*)d_in[17];
    const float* Wc2   = (const float*)d_in[18];
    const float* bc2   = (const float*)d_in[19];
    float* out = (float*)d_out;

    static bool attr_done = false;
    if (!attr_done) {
        cudaFuncSetAttribute(k_mlp, cudaFuncAttributeMaxDynamicSharedMemorySize, SMEM_BYTES);
        attr_done = true;
    }

    k_zero<<<1, 32>>>();
    k_route<<<NPTS / 256, 256>>>(pts, out);
    k_mlp<<<NCTA, NTHR, SMEM_BYTES>>>(pts, vds, aidx, app, W0, b0, Wpre, bpre,
                                      Wskip, bskip, Wpost, bpost, Wd, bd, Wf, bf,
                                      Wc1, bc1, Wc2, bc2, out);
}

// round 10
// speedup vs baseline: 2.0070x; 2.0070x over previous
#include <cuda_runtime.h>
#include <cuda_bf16.h>
#include <math.h>
#include <stdint.h>

#define NPTS 32768
#define TILE 64
#define NTHR 512
#define NCTA 148
#define CPE  81
#define NCHUNKS (8 * CPE)

__device__ int g_cnt[8];
__device__ int g_list[8 * NPTS];
__device__ __align__(16) __nv_bfloat16 Whi_g[(size_t)NCHUNKS * 10240];
__device__ __align__(16) __nv_bfloat16 Wlo_g[(size_t)NCHUNKS * 10240];

// ---- smem layout (bytes) ----
#define SB_WS    0                /* 2 x 40960 (hi 20480 + lo 20480) */
#define SB_AH    81920            /* 64 x 784 = 50176 */
#define SB_AL    132096           /* 50176 */
#define SB_GIDX  182272           /* 256 */
#define SB_WD    182528           /* 1024 */
#define SB_WC2   183552           /* 1552 */
#define SB_DENSP 185104           /* 2048 */
#define SB_COLP  187152           /* 3072 */
#define SMEM_BYTES 190224

// ---------------- helpers ----------------
__device__ __forceinline__ uint32_t smem_u32(const void* p) {
    uint32_t a;
    asm("{ .reg .u64 t; cvta.to.shared.u64 t, %1; cvt.u32.u64 %0, t; }" : "=r"(a) : "l"(p));
    return a;
}
__device__ __forceinline__ void cpasync16(uint32_t sa, const void* g) {
    asm volatile("cp.async.cg.shared.global [%0], [%1], 16;" :: "r"(sa), "l"(g));
}
__device__ __forceinline__ void cp_commit() { asm volatile("cp.async.commit_group;"); }
__device__ __forceinline__ void cp_wait0()  { asm volatile("cp.async.wait_group 0;"); }

__device__ __forceinline__ void mma16816(float* d, const uint32_t* a, uint32_t b0, uint32_t b1) {
    asm volatile("mma.sync.aligned.m16n8k16.row.col.f32.bf16.bf16.f32 "
                 "{%0,%1,%2,%3}, {%4,%5,%6,%7}, {%8,%9}, {%0,%1,%2,%3};"
                 : "+f"(d[0]), "+f"(d[1]), "+f"(d[2]), "+f"(d[3])
                 : "r"(a[0]), "r"(a[1]), "r"(a[2]), "r"(a[3]), "r"(b0), "r"(b1));
}

// fast accurate sincos: fp64 range reduction + fp32 poly (~1e-7 abs)
__device__ __forceinline__ void sincos_acc(float a, float* so, float* co) {
    double ad = (double)a;
    double kd = rint(ad * 0.6366197723675814);            // 2/pi
    double r  = fma(-kd, 1.5707963267948966, ad);
    r = fma(-kd, 6.123233995736766e-17, r);
    float rf = (float)r;
    float r2 = rf * rf;
    float sp = fmaf(r2, fmaf(r2, fmaf(r2, fmaf(r2, 2.7557314e-6f, -1.9841249e-4f),
                    8.3333338e-3f), -1.6666667e-1f), 1.0f);
    sp *= rf;
    float cp = fmaf(r2, fmaf(r2, fmaf(r2, fmaf(r2, -2.7557319e-7f, 2.4801587e-5f),
                    -1.3888889e-3f), 4.1666668e-2f), 0.0f);
    cp = fmaf(r2, cp, fmaf(r2, -0.5f, 1.0f));
    int q = ((int)kd) & 3;
    float s, c;
    if (q == 0)      { s =  sp; c =  cp; }
    else if (q == 1) { s =  cp; c = -sp; }
    else if (q == 2) { s = -sp; c = -cp; }
    else             { s = -cp; c =  sp; }
    *so = s; *co = c;
}

// ---------------- routing ----------------
__global__ void k_zero() { if (threadIdx.x < 8) g_cnt[threadIdx.x] = 0; }

__global__ void k_route(const float* __restrict__ pts, float* __restrict__ out) {
    int i = blockIdx.x * blockDim.x + threadIdx.x;
    if (i >= NPTS) return;
    float x = pts[3 * i], y = pts[3 * i + 1], z = pts[3 * i + 2];
    bool fg = (x >= -80.f) && (x <= 80.f) && (y >= -80.f) && (y <= 80.f)
           && (z >= -4.f) && (z <= 44.f);
    if (!fg) {
        out[i] = 0.f;
        out[NPTS + 3 * i] = 0.f; out[NPTS + 3 * i + 1] = 0.f; out[NPTS + 3 * i + 2] = 0.f;
        return;
    }
    int jx = (x > 0.f) ? 1 : 0;
    int iy = (y > 50.f) ? 3 : (y > 0.f) ? 2 : (y > -50.f) ? 1 : 0;
    int e = iy * 2 + jx;
    int pos = atomicAdd(&g_cnt[e], 1);
    g_list[e * NPTS + pos] = i;
}

// ==== weight prep: f32 [K][N] -> bf16 hi/lo transposed [256 n][32 k] chunks ====
// chunk row stride 40 halves (32 + 8 pad) = 80B. 81 chunks/expert.
__global__ void k_prep(const float* __restrict__ W0, const float* __restrict__ Wpre,
                       const float* __restrict__ Wskip, const float* __restrict__ Wpost,
                       const float* __restrict__ Wf, const float* __restrict__ Wc1) {
    int ch = blockIdx.x;
    int e = ch / CPE, r = ch % CPE;
    const float* src; int K, N, k0;
    if (r < 4)       { src = W0    + (size_t)e * 111 * 256; K = 111; N = 256; k0 = r * 32; }
    else if (r < 28) { int i = (r - 4) >> 3;  src = Wpre  + ((size_t)e * 3 + i) * 65536; K = 256; N = 256; k0 = ((r - 4) & 7) * 32; }
    else if (r < 40) { src = Wskip + (size_t)e * 367 * 256; K = 367; N = 256; k0 = (r - 28) * 32; }
    else if (r < 64) { int i = (r - 40) >> 3; src = Wpost + ((size_t)e * 3 + i) * 65536; K = 256; N = 256; k0 = ((r - 40) & 7) * 32; }
    else if (r < 72) { src = Wf    + (size_t)e * 65536;     K = 256; N = 256; k0 = (r - 64) * 32; }
    else             { src = Wc1   + (size_t)e * 283 * 128; K = 283; N = 128; k0 = (r - 72) * 32; }
    int n = threadIdx.x;   // 0..255
    __nv_bfloat16 hi[32], lo[32];
#pragma unroll 8
    for (int kk = 0; kk < 32; kk++) {
        int k = k0 + kk;
        float v = (k < K && n < N) ? src[(size_t)k * N + n] : 0.f;
        __nv_bfloat16 h = __float2bfloat16(v);
        hi[kk] = h;
        lo[kk] = __float2bfloat16(v - __bfloat162float(h));
    }
    char* dh = (char*)Whi_g + (size_t)ch * 20480 + n * 80;
    char* dl = (char*)Wlo_g + (size_t)ch * 20480 + n * 80;
#pragma unroll
    for (int g = 0; g < 4; g++) {
        *(uint4*)(dh + g * 16) = *(uint4*)&hi[g * 8];
        *(uint4*)(dl + g * 16) = *(uint4*)&lo[g * 8];
    }
}

// ---------------- W chunk staging ----------------
__device__ __forceinline__ void stageW(char* smp, int buf, int chunk, int tid) {
    const char* sh = (const char*)Whi_g + (size_t)chunk * 20480;
    const char* sl = (const char*)Wlo_g + (size_t)chunk * 20480;
    uint32_t sa = smem_u32(smp + SB_WS + buf * 40960);
#pragma unroll
    for (int u = tid; u < 1280; u += NTHR) {
        cpasync16(sa + u * 16, sh + u * 16);
        cpasync16(sa + 20480 + u * 16, sl + u * 16);
    }
}

// ---------------- one GEMM layer over a 64-pt tile ----------------
// mode: 0 relu+writeA ; 1 relu+writeA+density ; 2 writeA no relu ; 3 relu+color (N=128)
__device__ __noinline__ void gemm_layer(char* smp, int cbase, int nch, int acolb,
                                        int mode, const float* __restrict__ bias) {
    const int tid = threadIdx.x;
    const int w = tid >> 5, l = tid & 31;
    const int m = w & 1, ng = w >> 1;
    const int gid = l >> 2, tig = l & 3;
    const bool active = (mode == 3) ? (ng < 4) : true;

    float acc[2][4][4];
#pragma unroll
    for (int mt = 0; mt < 2; mt++)
#pragma unroll
        for (int nt = 0; nt < 4; nt++)
#pragma unroll
            for (int j = 0; j < 4; j++) acc[mt][nt][j] = 0.f;

    stageW(smp, 0, cbase, tid);
    cp_commit();

    // A fragment: thread (gid, tig) covers rows {gid, gid+8}, k halves {2*tig, 2*tig+1}
    // and {2*tig+8, 2*tig+9}  ->  byte offsets +4*tig and +4*tig+16.
    const uint32_t arow0 = (uint32_t)((m * 32 + gid) * 784 + acolb + tig * 4);
    const uint32_t brow  = (uint32_t)((ng * 32 + gid) * 80 + tig * 4);

    for (int c = 0; c < nch; c++) {
        cp_wait0();
        __syncthreads();
        if (c + 1 < nch) { stageW(smp, (c + 1) & 1, cbase + c + 1, tid); cp_commit(); }
        if (active) {
            const char* Wb = smp + SB_WS + (c & 1) * 40960;
#pragma unroll
            for (int ks2 = 0; ks2 < 2; ks2++) {
                uint32_t kb = (uint32_t)((c * 2 + ks2) * 32);
                uint32_t ah[2][4], al[2][4];
#pragma unroll
                for (int mt = 0; mt < 2; mt++) {
                    uint32_t r0 = arow0 + (uint32_t)(mt * 16 * 784) + kb;
                    uint32_t r1 = r0 + 8u * 784u;
                    ah[mt][0] = *(const uint32_t*)(smp + SB_AH + r0);
                    ah[mt][1] = *(const uint32_t*)(smp + SB_AH + r1);
                    ah[mt][2] = *(const uint32_t*)(smp + SB_AH + r0 + 16);
                    ah[mt][3] = *(const uint32_t*)(smp + SB_AH + r1 + 16);
                    al[mt][0] = *(const uint32_t*)(smp + SB_AL + r0);
                    al[mt][1] = *(const uint32_t*)(smp + SB_AL + r1);
                    al[mt][2] = *(const uint32_t*)(smp + SB_AL + r0 + 16);
                    al[mt][3] = *(const uint32_t*)(smp + SB_AL + r1 + 16);
                }
#pragma unroll
                for (int nt = 0; nt < 4; nt++) {
                    uint32_t bo = brow + (uint32_t)(nt * 8 * 80 + ks2 * 32);
                    uint32_t bh0 = *(const uint32_t*)(Wb + bo);
                    uint32_t bh1 = *(const uint32_t*)(Wb + bo + 16);
                    uint32_t bl0 = *(const uint32_t*)(Wb + 20480 + bo);
                    uint32_t bl1 = *(const uint32_t*)(Wb + 20480 + bo + 16);
#pragma unroll
                    for (int mt = 0; mt < 2; mt++) {
                        mma16816(acc[mt][nt], ah[mt], bh0, bh1);
                        mma16816(acc[mt][nt], al[mt], bh0, bh1);
                        mma16816(acc[mt][nt], ah[mt], bl0, bl1);
                    }
                }
            }
        }
    }

    __syncthreads();   // all A reads done before in-place writeback
    if (active) {
        float dp[2][2];
        float cp3[2][2][3];
#pragma unroll
        for (int mt = 0; mt < 2; mt++)
#pragma unroll
            for (int hf = 0; hf < 2; hf++) {
                dp[mt][hf] = 0.f;
                cp3[mt][hf][0] = 0.f; cp3[mt][hf][1] = 0.f; cp3[mt][hf][2] = 0.f;
            }
        float* WdS  = (float*)(smp + SB_WD);
        float* Wc2S = (float*)(smp + SB_WC2);
#pragma unroll
        for (int nt = 0; nt < 4; nt++) {
            int c0 = ng * 32 + nt * 8 + 2 * tig;
            float b0v = __ldg(bias + c0), b1v = __ldg(bias + c0 + 1);
#pragma unroll
            for (int mt = 0; mt < 2; mt++) {
                float v0 = acc[mt][nt][0] + b0v;
                float v1 = acc[mt][nt][1] + b1v;
                float v2 = acc[mt][nt][2] + b0v;
                float v3 = acc[mt][nt][3] + b1v;
                if (mode != 2) {
                    v0 = fmaxf(v0, 0.f); v1 = fmaxf(v1, 0.f);
                    v2 = fmaxf(v2, 0.f); v3 = fmaxf(v3, 0.f);
                }
                if (mode == 1) {
                    dp[mt][0] += v0 * WdS[c0] + v1 * WdS[c0 + 1];
                    dp[mt][1] += v2 * WdS[c0] + v3 * WdS[c0 + 1];
                }
                if (mode == 3) {
#pragma unroll
                    for (int chn = 0; chn < 3; chn++) {
                        cp3[mt][0][chn] += v0 * Wc2S[c0 * 3 + chn] + v1 * Wc2S[(c0 + 1) * 3 + chn];
                        cp3[mt][1][chn] += v2 * Wc2S[c0 * 3 + chn] + v3 * Wc2S[(c0 + 1) * 3 + chn];
                    }
                } else {
                    uint32_t off0 = (uint32_t)((m * 32 + mt * 16 + gid) * 784 + c0 * 2);
                    uint32_t off1 = off0 + 8u * 784u;
                    __nv_bfloat16 h0 = __float2bfloat16(v0), h1 = __float2bfloat16(v1);
                    __nv_bfloat16 h2 = __float2bfloat16(v2), h3 = __float2bfloat16(v3);
                    __nv_bfloat162 H0 = __halves2bfloat162(h0, h1);
                    __nv_bfloat162 H1 = __halves2bfloat162(h2, h3);
                    __nv_bfloat162 L0 = __halves2bfloat162(
                        __float2bfloat16(v0 - __bfloat162float(h0)),
                        __float2bfloat16(v1 - __bfloat162float(h1)));
                    __nv_bfloat162 L1 = __halves2bfloat162(
                        __float2bfloat16(v2 - __bfloat162float(h2)),
                        __float2bfloat16(v3 - __bfloat162float(h3)));
                    *(uint32_t*)(smp + SB_AH + off0) = *(uint32_t*)&H0;
                    *(uint32_t*)(smp + SB_AH + off1) = *(uint32_t*)&H1;
                    *(uint32_t*)(smp + SB_AL + off0) = *(uint32_t*)&L0;
                    *(uint32_t*)(smp + SB_AL + off1) = *(uint32_t*)&L1;
                }
            }
        }
        if (mode == 1) {
#pragma unroll
            for (int mt = 0; mt < 2; mt++)
#pragma unroll
                for (int hf = 0; hf < 2; hf++) {
                    float s = dp[mt][hf];
                    s += __shfl_xor_sync(0xffffffffu, s, 1);
                    s += __shfl_xor_sync(0xffffffffu, s, 2);
                    if (tig == 0)
                        ((float*)(smp + SB_DENSP))[ng * 64 + m * 32 + mt * 16 + hf * 8 + gid] = s;
                }
        }
        if (mode == 3) {
#pragma unroll
            for (int mt = 0; mt < 2; mt++)
#pragma unroll
                for (int hf = 0; hf < 2; hf++)
#pragma unroll
                    for (int chn = 0; chn < 3; chn++) {
                        float s = cp3[mt][hf][chn];
                        s += __shfl_xor_sync(0xffffffffu, s, 1);
                        s += __shfl_xor_sync(0xffffffffu, s, 2);
                        if (tig == 0)
                            ((float*)(smp + SB_COLP))[(ng * 64 + m * 32 + mt * 16 + hf * 8 + gid) * 3 + chn] = s;
                    }
        }
    }
    __syncthreads();
}

// smem A-tile store (bf16 hi + lo)
__device__ __forceinline__ void a_store(char* smp, int p, int col, float v) {
    uint32_t off = (uint32_t)(p * 784 + col * 2);
    __nv_bfloat16 h = __float2bfloat16(v);
    *(__nv_bfloat16*)(smp + SB_AH + off) = h;
    *(__nv_bfloat16*)(smp + SB_AL + off) = __float2bfloat16(v - __bfloat162float(h));
}

// ---------------- main MLP kernel ----------------
__global__ void __launch_bounds__(NTHR, 1) k_mlp(
    const float* __restrict__ pts, const float* __restrict__ vds,
    const int* __restrict__ aidx, const float* __restrict__ app,
    const float* __restrict__ b0, const float* __restrict__ bpre,
    const float* __restrict__ bskip, const float* __restrict__ bpost,
    const float* __restrict__ Wd, const float* __restrict__ bd,
    const float* __restrict__ bf, const float* __restrict__ bc1,
    const float* __restrict__ Wc2, const float* __restrict__ bc2,
    float* __restrict__ out) {
    extern __shared__ char smp[];
    const int tid = threadIdx.x;

    int cnt8[8], tb[8], tot = 0;
#pragma unroll
    for (int e8 = 0; e8 < 8; e8++) {
        cnt8[e8] = g_cnt[e8]; tb[e8] = tot;
        tot += (cnt8[e8] + TILE - 1) / TILE;
    }
    int* gidx = (int*)(smp + SB_GIDX);
    float* WdS  = (float*)(smp + SB_WD);
    float* Wc2S = (float*)(smp + SB_WC2);

    for (int tile = blockIdx.x; tile < tot; tile += gridDim.x) {
        int e = 0;
#pragma unroll
        for (int e8 = 1; e8 < 8; e8++) if (tile >= tb[e8]) e = e8;
        const int base = (tile - tb[e]) * TILE;
        const int npts = min(TILE, cnt8[e] - base);
        const int eb = e * CPE;

        // zero A hi+lo (100352 B = 6272 uint4)
        for (int u = tid; u < 6272; u += NTHR)
            ((uint4*)(smp + SB_AH))[u] = make_uint4(0, 0, 0, 0);
        if (tid < 256) WdS[tid] = Wd[e * 256 + tid];
        for (int j = tid; j < 387; j += NTHR)
            Wc2S[j] = (j < 384) ? Wc2[e * 384 + j] : bc2[e * 3 + (j - 384)];
        __syncthreads();

        // posenc + appearance -> A cols 256..366 (8 threads per point)
        {
            int pt = tid >> 3, q = tid & 7;
            if (pt < npts) {
                int g = g_list[e * NPTS + base + pt];
                float px = pts[3 * g], py = pts[3 * g + 1], pz = pts[3 * g + 2];
                if (q == 0) {
                    gidx[pt] = g;
                    a_store(smp, pt, 256, px); a_store(smp, pt, 257, py); a_store(smp, pt, 258, pz);
                }
                for (int i = q; i < 10; i += 8) {
                    float f = (float)exp2((double)i * (10.0 / 9.0));
                    int r = 256 + 3 + 6 * i;
                    float s, c;
                    sincos_acc(f * px, &s, &c); a_store(smp, pt, r + 0, s); a_store(smp, pt, r + 3, c);
                    sincos_acc(f * py, &s, &c); a_store(smp, pt, r + 1, s); a_store(smp, pt, r + 4, c);
                    sincos_acc(f * pz, &s, &c); a_store(smp, pt, r + 2, s); a_store(smp, pt, r + 5, c);
                }
                int ai = aidx[g];
                const float* a = app + ((size_t)e * 1000 + ai) * 48;
                for (int j = q; j < 48; j += 8) a_store(smp, pt, 256 + 63 + j, a[j]);
            } else if (q == 0) gidx[pt] = 0;
        }
        __syncthreads();

        // trunk
        gemm_layer(smp, eb + 0, 4, 512, 0, b0 + e * 256);                 // W0 (A cols 256+)
        for (int i = 0; i < 3; i++)
            gemm_layer(smp, eb + 4 + 8 * i, 8, 0, 0, bpre + (e * 3 + i) * 256);
        gemm_layer(smp, eb + 28, 12, 0, 0, bskip + e * 256);              // skip (K=384)

        // dir-enc overwrites x0 region cols 256..287 (also zero stale 283..287)
        {
            int pt = tid >> 3, q = tid & 7;
            if (pt < npts) {
                int g = gidx[pt];
                float vx = vds[3 * g], vy = vds[3 * g + 1], vz = vds[3 * g + 2];
                if (q < 4) {
                    float f = (float)exp2((double)q * (4.0 / 3.0));
                    int r = 256 + 3 + 6 * q;
                    float s, c;
                    sincos_acc(f * vx, &s, &c); a_store(smp, pt, r + 0, s); a_store(smp, pt, r + 3, c);
                    sincos_acc(f * vy, &s, &c); a_store(smp, pt, r + 1, s); a_store(smp, pt, r + 4, c);
                    sincos_acc(f * vz, &s, &c); a_store(smp, pt, r + 2, s); a_store(smp, pt, r + 5, c);
                } else if (q == 4) {
                    a_store(smp, pt, 256, vx); a_store(smp, pt, 257, vy); a_store(smp, pt, 258, vz);
                } else if (q == 5) {
                    for (int j = 283; j < 288; j++) a_store(smp, pt, j, 0.f);
                }
            }
        }
        __syncthreads();

        for (int i = 0; i < 3; i++)
            gemm_layer(smp, eb + 40 + 8 * i, 8, 0, (i == 2) ? 1 : 0, bpost + (e * 3 + i) * 256);

        // density finalize
        if (tid < 64) {
            float* dps = (float*)(smp + SB_DENSP);
            float s = bd[e];
#pragma unroll
            for (int ngx = 0; ngx < 8; ngx++) s += dps[ngx * 64 + tid];
            if (tid < npts) out[gidx[tid]] = fmaxf(s, 0.f);
        }

        gemm_layer(smp, eb + 64, 8, 0, 2, bf + e * 256);                   // feature
        gemm_layer(smp, eb + 72, 9, 0, 3, bc1 + e * 128);                  // color hidden

        // color finalize
        if (tid < 192) {
            int pt = tid / 3, chn = tid - 3 * pt;
            float* cps = (float*)(smp + SB_COLP);
            float s = Wc2S[384 + chn];
#pragma unroll
            for (int ngx = 0; ngx < 4; ngx++) s += cps[(ngx * 64 + pt) * 3 + chn];
            if (pt < npts) out[NPTS + 3 * gidx[pt] + chn] = 1.f / (1.f + expf(-s));
        }
        __syncthreads();   // smem reused next tile
    }
}

// ---------------- launch ----------------
extern "C" void kernel_launch(void* const* d_in, const int* in_sizes, int n_in,
                              void* d_out, int out_size) {
    const float* pts   = (const float*)d_in[0];
    const float* vds   = (const float*)d_in[1];
    const int*   aidx  = (const int*)d_in[2];
    const float* app   = (const float*)d_in[3];
    const float* W0    = (const float*)d_in[4];
    const float* b0    = (const float*)d_in[5];
    const float* Wpre  = (const float*)d_in[6];
    const float* bpre  = (const float*)d_in[7];
    const float* Wskip = (const float*)d_in[8];
    const float* bskip = (const float*)d_in[9];
    const float* Wpost = (const float*)d_in[10];
    const float* bpost = (const float*)d_in[11];
    const float* Wd    = (const float*)d_in[12];
    const float* bd    = (const float*)d_in[13];
    const float* Wf    = (const float*)d_in[14];
    const float* bf    = (const float*)d_in[15];
    const float* Wc1   = (const float*)d_in[16];
    const float* bc1   = (const float*)d_in[17];
    const float* Wc2   = (const float*)d_in[18];
    const float* bc2   = (const float*)d_in[19];
    float* out = (float*)d_out;

    static bool attr_done = false;
    if (!attr_done) {
        cudaFuncSetAttribute(k_mlp, cudaFuncAttributeMaxDynamicSharedMemorySize, SMEM_BYTES);
        attr_done = true;
    }

    k_prep<<<NCHUNKS, 256>>>(W0, Wpre, Wskip, Wpost, Wf, Wc1);
    k_zero<<<1, 32>>>();
    k_route<<<NPTS / 256, 256>>>(pts, out);
    k_mlp<<<NCTA, NTHR, SMEM_BYTES>>>(pts, vds, aidx, app, b0, bpre, bskip, bpost,
                                      Wd, bd, bf, bc1, Wc2, bc2, out);
}